// round 4
// baseline (speedup 1.0000x reference)
#include <cuda_runtime.h>
#include <cuda_bf16.h>
#include <cstdint>

// ===================== problem dims =====================
#define BDIM 4096
#define IDIM 1024
#define HDIM 1024
#define KDIM 2048   // I + H
#define NDIM 4096   // 4 * H, INTERLEAVED: n = j*4 + g  (g in {f,i,o,c})

// ===================== device scratch (static, allowed) =====================
__device__ __align__(256) __nv_bfloat16 g_Ahi[(size_t)BDIM * KDIM];
__device__ __align__(256) __nv_bfloat16 g_Alo[(size_t)BDIM * KDIM];
__device__ __align__(256) __nv_bfloat16 g_Whi[(size_t)NDIM * KDIM];
__device__ __align__(256) __nv_bfloat16 g_Wlo[(size_t)NDIM * KDIM];
__device__ __align__(256) float         g_bias[NDIM];   // interleaved j*4+g
__device__ __align__(256) float         g_mask[BDIM];

// ===================== small PTX helpers (sm_80+ features only) =====================
__device__ __forceinline__ uint32_t smem_to_u32(const void* p) {
    uint32_t a;
    asm("{ .reg .u64 t; cvta.to.shared.u64 t, %1; cvt.u32.u64 %0, t; }" : "=r"(a) : "l"(p));
    return a;
}

__device__ __forceinline__ void cp16(uint32_t saddr, const void* g) {
    asm volatile("cp.async.cg.shared.global [%0], [%1], 16;" :: "r"(saddr), "l"(g) : "memory");
}

#define CP_COMMIT() asm volatile("cp.async.commit_group;" ::: "memory")
#define CP_WAIT(N)  asm volatile("cp.async.wait_group %0;" :: "n"(N) : "memory")

__device__ __forceinline__ void ldsm4(uint32_t* r, uint32_t addr) {
    asm volatile("ldmatrix.sync.aligned.m8n8.x4.shared.b16 {%0,%1,%2,%3}, [%4];"
                 : "=r"(r[0]), "=r"(r[1]), "=r"(r[2]), "=r"(r[3]) : "r"(addr));
}

__device__ __forceinline__ void mma16816(float* c, const uint32_t* a, uint32_t b0, uint32_t b1) {
    asm volatile(
        "mma.sync.aligned.m16n8k16.row.col.f32.bf16.bf16.f32 "
        "{%0,%1,%2,%3}, {%4,%5,%6,%7}, {%8,%9}, {%0,%1,%2,%3};"
        : "+f"(c[0]), "+f"(c[1]), "+f"(c[2]), "+f"(c[3])
        : "r"(a[0]), "r"(a[1]), "r"(a[2]), "r"(a[3]), "r"(b0), "r"(b1));
}

// ===================== split-bf16 helpers =====================
__device__ __forceinline__ uint32_t pk2(__nv_bfloat16 a, __nv_bfloat16 b) {
    __nv_bfloat162 t = __halves2bfloat162(a, b);
    return *reinterpret_cast<uint32_t*>(&t);
}

__device__ __forceinline__ float split_store4(float4 v, __nv_bfloat16* hip, __nv_bfloat16* lop) {
    __nv_bfloat16 h0 = __float2bfloat16(v.x), h1 = __float2bfloat16(v.y),
                  h2 = __float2bfloat16(v.z), h3 = __float2bfloat16(v.w);
    float l0 = v.x - __bfloat162float(h0), l1 = v.y - __bfloat162float(h1),
          l2 = v.z - __bfloat162float(h2), l3 = v.w - __bfloat162float(h3);
    uint2 hv = make_uint2(pk2(h0, h1), pk2(h2, h3));
    uint2 lv = make_uint2(pk2(__float2bfloat16(l0), __float2bfloat16(l1)),
                          pk2(__float2bfloat16(l2), __float2bfloat16(l3)));
    *reinterpret_cast<uint2*>(hip) = hv;
    *reinterpret_cast<uint2*>(lop) = lv;
    return v.x * v.x + v.y * v.y + v.z * v.z + v.w * v.w;
}

// ===================== kernel 1: convert A = [x | h_prev] + silence mask =====================
__global__ void convert_A_kernel(const float* __restrict__ x, const float* __restrict__ h) {
    int m = blockIdx.x;
    int t = threadIdx.x;  // 256
    float4 vx = reinterpret_cast<const float4*>(x)[(size_t)m * 256 + t];
    float ss = split_store4(vx, g_Ahi + (size_t)m * KDIM + 4 * t,
                                g_Alo + (size_t)m * KDIM + 4 * t);
    float4 vh = reinterpret_cast<const float4*>(h)[(size_t)m * 256 + t];
    split_store4(vh, g_Ahi + (size_t)m * KDIM + IDIM + 4 * t,
                     g_Alo + (size_t)m * KDIM + IDIM + 4 * t);

    __shared__ float red[256];
    red[t] = ss;
    __syncthreads();
    for (int s = 128; s > 0; s >>= 1) {
        if (t < s) red[t] += red[t + s];
        __syncthreads();
    }
    if (t == 0) g_mask[m] = (red[0] > 1e-6f) ? 1.0f : 0.0f;  // norm > 0.001
}

// ===================== kernel 2: convert packed weights (interleaved rows) =====================
__global__ void convert_W_kernel(const float* __restrict__ Wf, const float* __restrict__ Wi,
                                 const float* __restrict__ Wo, const float* __restrict__ Wc,
                                 const float* __restrict__ Vf, const float* __restrict__ Vi,
                                 const float* __restrict__ Vo, const float* __restrict__ Vc) {
    int n = blockIdx.x;     // 0..4095 (gate-major source index)
    int t = threadIdx.x;    // 256
    int g = n >> 10, j = n & 1023;
    int row = (j << 2) | g;  // interleaved destination row
    const float* W = (g == 0) ? Wf : (g == 1) ? Wi : (g == 2) ? Wo : Wc;
    const float* V = (g == 0) ? Vf : (g == 1) ? Vi : (g == 2) ? Vo : Vc;
    float4 vw = reinterpret_cast<const float4*>(W)[(size_t)j * 256 + t];
    split_store4(vw, g_Whi + (size_t)row * KDIM + 4 * t,
                     g_Wlo + (size_t)row * KDIM + 4 * t);
    float4 vv = reinterpret_cast<const float4*>(V)[(size_t)j * 256 + t];
    split_store4(vv, g_Whi + (size_t)row * KDIM + IDIM + 4 * t,
                     g_Wlo + (size_t)row * KDIM + IDIM + 4 * t);
}

// ===================== kernel 3: combined bias (interleaved) =====================
__global__ void bias_kernel(const float* __restrict__ bWf, const float* __restrict__ bVf, const float* __restrict__ bf_,
                            const float* __restrict__ bWi, const float* __restrict__ bVi, const float* __restrict__ bi_,
                            const float* __restrict__ bWo, const float* __restrict__ bVo, const float* __restrict__ bo_,
                            const float* __restrict__ bWc, const float* __restrict__ bVc, const float* __restrict__ bc_) {
    int n = blockIdx.x * blockDim.x + threadIdx.x;
    if (n >= NDIM) return;
    int g = n >> 10, j = n & 1023;
    const float* a = (g == 0) ? bWf : (g == 1) ? bWi : (g == 2) ? bWo : bWc;
    const float* b = (g == 0) ? bVf : (g == 1) ? bVi : (g == 2) ? bVo : bVc;
    const float* c = (g == 0) ? bf_ : (g == 1) ? bi_ : (g == 2) ? bo_ : bc_;
    g_bias[(j << 2) | g] = a[j] + b[j] + c[j];
}

// ===================== kernel 4: pipelined GEMM + fused LSTM epilogue =====================
// gates = Ahi*Whi^T + Ahi*Wlo^T + Alo*Whi^T  (fp32 accum), then activations -> out
#define BM 128
#define BN 128
#define BK 32
#define NK (KDIM / BK)         // 64 k-tiles
#define TPITCH 80              // 64B data + 16B pad -> conflict-free ldmatrix
#define BUF_BYTES (128 * TPITCH)        // 10240
#define STAGE_BYTES (4 * BUF_BYTES)     // 40960: Ahi, Alo, Whi, Wlo
#define NSTAGES 4
#define GEMM_SMEM (NSTAGES * STAGE_BYTES)  // 163840
#define EPITCH 132             // floats per gates row in smem epilogue (16B aligned)

__device__ __forceinline__ void load_stage(char* smem, uint32_t sb, int stage, int kt, int tid,
                                           const __nv_bfloat16* Ahi, const __nv_bfloat16* Alo,
                                           const __nv_bfloat16* Whi, const __nv_bfloat16* Wlo) {
    uint32_t s0 = sb + (uint32_t)stage * STAGE_BYTES;
    int r = tid >> 2, c = tid & 3;                    // row 0..127, 16B chunk 0..3
    size_t goff = (size_t)r * KDIM + (size_t)kt * BK + c * 8;
    uint32_t soff = (uint32_t)(r * TPITCH + c * 16);
    cp16(s0 + soff,                 Ahi + goff);
    cp16(s0 + BUF_BYTES + soff,     Alo + goff);
    cp16(s0 + 2 * BUF_BYTES + soff, Whi + goff);
    cp16(s0 + 3 * BUF_BYTES + soff, Wlo + goff);
    CP_COMMIT();
}

__global__ void __launch_bounds__(512, 1) gemm_kernel(const float* __restrict__ c_prev,
                                                      float* __restrict__ out, int n_out) {
    extern __shared__ char smem[];
    uint32_t sb = smem_to_u32(smem);
    int tid = threadIdx.x, wid = tid >> 5, lid = tid & 31;
    int m0 = blockIdx.y * BM;
    int n0 = blockIdx.x * BN;
    int j_base = n0 >> 2;        // interleaved: 32 j's per CTA tile
    int wm = (wid >> 2) * 32;    // 4x4 warp grid, warp tile 32x32
    int wn = (wid & 3) * 32;

    const __nv_bfloat16* Ahi = g_Ahi + (size_t)m0 * KDIM;
    const __nv_bfloat16* Alo = g_Alo + (size_t)m0 * KDIM;
    const __nv_bfloat16* Whi = g_Whi + (size_t)n0 * KDIM;
    const __nv_bfloat16* Wlo = g_Wlo + (size_t)n0 * KDIM;

    float acc[2][4][4];
    #pragma unroll
    for (int i = 0; i < 2; ++i)
        #pragma unroll
        for (int j = 0; j < 4; ++j)
            #pragma unroll
            for (int k = 0; k < 4; ++k) acc[i][j][k] = 0.0f;

    int lrow = lid & 15;
    uint32_t lchunk = (uint32_t)((lid >> 4) << 4);

    // prologue: stages 0..2
    load_stage(smem, sb, 0, 0, tid, Ahi, Alo, Whi, Wlo);
    load_stage(smem, sb, 1, 1, tid, Ahi, Alo, Whi, Wlo);
    load_stage(smem, sb, 2, 2, tid, Ahi, Alo, Whi, Wlo);

    for (int kt = 0; kt < NK; ++kt) {
        // tapered wait: pending groups allowed = min(2, NK-1-kt)
        if (kt < NK - 2)      { CP_WAIT(2); }
        else if (kt == NK - 2){ CP_WAIT(1); }
        else                  { CP_WAIT(0); }
        __syncthreads();   // all threads' copies for tile kt visible; frees buf (kt+3)%4

        uint32_t cur = sb + (uint32_t)(kt & (NSTAGES - 1)) * STAGE_BYTES;
        uint32_t sAhi = cur;
        uint32_t sAlo = cur + BUF_BYTES;
        uint32_t sWhi = cur + 2 * BUF_BYTES;
        uint32_t sWlo = cur + 3 * BUF_BYTES;

        #pragma unroll
        for (int ks = 0; ks < 2; ++ks) {
            uint32_t kb = (uint32_t)(ks * 32) + lchunk;

            uint32_t ahi[2][4], w0[2][4];
            #pragma unroll
            for (int am = 0; am < 2; ++am)
                ldsm4(ahi[am], sAhi + (uint32_t)(wm + am * 16 + lrow) * TPITCH + kb);
            #pragma unroll
            for (int bt = 0; bt < 2; ++bt)
                ldsm4(w0[bt], sWhi + (uint32_t)(wn + bt * 16 + lrow) * TPITCH + kb);

            // pass 1: Ahi * Whi
            #pragma unroll
            for (int am = 0; am < 2; ++am)
                #pragma unroll
                for (int bt = 0; bt < 2; ++bt) {
                    mma16816(acc[am][2 * bt],     ahi[am], w0[bt][0], w0[bt][2]);
                    mma16816(acc[am][2 * bt + 1], ahi[am], w0[bt][1], w0[bt][3]);
                }

            // pass 2: Ahi * Wlo
            uint32_t w1[2][4];
            #pragma unroll
            for (int bt = 0; bt < 2; ++bt)
                ldsm4(w1[bt], sWlo + (uint32_t)(wn + bt * 16 + lrow) * TPITCH + kb);
            #pragma unroll
            for (int am = 0; am < 2; ++am)
                #pragma unroll
                for (int bt = 0; bt < 2; ++bt) {
                    mma16816(acc[am][2 * bt],     ahi[am], w1[bt][0], w1[bt][2]);
                    mma16816(acc[am][2 * bt + 1], ahi[am], w1[bt][1], w1[bt][3]);
                }

            // pass 3: Alo * Whi
            uint32_t alo[2][4];
            #pragma unroll
            for (int am = 0; am < 2; ++am)
                ldsm4(alo[am], sAlo + (uint32_t)(wm + am * 16 + lrow) * TPITCH + kb);
            #pragma unroll
            for (int am = 0; am < 2; ++am)
                #pragma unroll
                for (int bt = 0; bt < 2; ++bt) {
                    mma16816(acc[am][2 * bt],     alo[am], w0[bt][0], w0[bt][2]);
                    mma16816(acc[am][2 * bt + 1], alo[am], w0[bt][1], w0[bt][3]);
                }
        }

        // prefetch tile kt+3 (after compute; top barrier of next iter protects WAR)
        if (kt + 3 < NK)
            load_stage(smem, sb, (kt + 3) & (NSTAGES - 1), kt + 3, tid, Ahi, Alo, Whi, Wlo);
    }

    // ===== fused epilogue: acc -> smem -> activations -> out =====
    __syncthreads();   // done reading stage buffers; reuse smem for gates
    float* sg = reinterpret_cast<float*>(smem);   // [128][EPITCH]
    int gid = lid >> 2, tig = lid & 3;
    #pragma unroll
    for (int am = 0; am < 2; ++am) {
        #pragma unroll
        for (int bn = 0; bn < 4; ++bn) {
            const float* c = acc[am][bn];
            int row = wm + am * 16 + gid;
            int col = wn + bn * 8 + tig * 2;
            sg[row * EPITCH + col]       = c[0];
            sg[row * EPITCH + col + 1]   = c[1];
            sg[(row + 8) * EPITCH + col]     = c[2];
            sg[(row + 8) * EPITCH + col + 1] = c[3];
        }
    }
    __syncthreads();

    const int BH = BDIM * HDIM;
    #pragma unroll
    for (int i = 0; i < 8; ++i) {
        int idx = tid + i * 512;       // 128 rows x 32 j
        int row = idx >> 5, lj = idx & 31;
        float4 gv = *reinterpret_cast<const float4*>(&sg[row * EPITCH + lj * 4]);
        int jg = j_base + lj;
        float4 bv = *reinterpret_cast<const float4*>(&g_bias[jg * 4]);
        float fp = gv.x + bv.x, ip = gv.y + bv.y, op = gv.z + bv.z, cp = gv.w + bv.w;
        float ft = 1.0f / (1.0f + expf(-fp));
        float it = 1.0f / (1.0f + expf(-ip));
        float ot = 1.0f / (1.0f + expf(-op));
        float ct = tanhf(cp);
        int m = m0 + row;
        int oidx = m * HDIM + jg;
        float cpv = c_prev[oidx];
        float cn = ft * cpv + it * cpv + g_mask[m] * (it * ct);
        float hn = ot * tanhf(cn);
        out[oidx] = hn;
        if (BH + oidx < n_out)     out[BH + oidx] = cn;
        if (2 * BH + oidx < n_out) out[2 * BH + oidx] = ct;
    }
}

// ===================== launcher =====================
extern "C" void kernel_launch(void* const* d_in, const int* in_sizes, int n_in,
                              void* d_out, int out_size) {
    (void)n_in;
    const float* x      = (const float*)d_in[0];
    const float* h_prev = (const float*)d_in[1];
    const float* c_prev = (const float*)d_in[2];
    // d_in[3] = c_prev_tilde_dummy (unused)

    // Input order detection (dict order vs signature order); see round-2 notes.
    const float *W[4], *V[4], *bW[4], *bV[4], *bx[4];
    if (in_sizes[8] > 100000) {
        for (int g = 0; g < 4; ++g) {   // dict order
            W[g]  = (const float*)d_in[4 + 4 * g];
            bW[g] = (const float*)d_in[5 + 4 * g];
            V[g]  = (const float*)d_in[6 + 4 * g];
            bV[g] = (const float*)d_in[7 + 4 * g];
            bx[g] = (const float*)d_in[20 + g];
        }
    } else {
        for (int g = 0; g < 4; ++g) {   // signature order
            W[g]  = (const float*)d_in[4 + 5 * g];
            bW[g] = (const float*)d_in[5 + 5 * g];
            V[g]  = (const float*)d_in[6 + 5 * g];
            bV[g] = (const float*)d_in[7 + 5 * g];
            bx[g] = (const float*)d_in[8 + 5 * g];
        }
    }

    convert_A_kernel<<<BDIM, 256>>>(x, h_prev);
    convert_W_kernel<<<NDIM, 256>>>(W[0], W[1], W[2], W[3], V[0], V[1], V[2], V[3]);
    bias_kernel<<<NDIM / 256, 256>>>(bW[0], bV[0], bx[0], bW[1], bV[1], bx[1],
                                     bW[2], bV[2], bx[2], bW[3], bV[3], bx[3]);

    static bool attr_set = false;
    if (!attr_set) {
        cudaFuncSetAttribute(gemm_kernel, cudaFuncAttributeMaxDynamicSharedMemorySize,
                             (int)GEMM_SMEM);
        attr_set = true;
    }
    gemm_kernel<<<dim3(NDIM / BN, BDIM / BM), 512, GEMM_SMEM>>>(c_prev, (float*)d_out, out_size);
}

// round 5
// speedup vs baseline: 1.2799x; 1.2799x over previous
#include <cuda_runtime.h>
#include <cuda_bf16.h>
#include <cstdint>

// ===================== problem dims =====================
#define BDIM 4096
#define IDIM 1024
#define HDIM 1024
#define KDIM 2048   // I + H
#define NDIM 4096   // 4 * H, INTERLEAVED: n = j*4 + g  (g in {f,i,o,c})

// ===================== device scratch (static, allowed) =====================
__device__ __align__(256) __nv_bfloat16 g_Ahi[(size_t)BDIM * KDIM];
__device__ __align__(256) __nv_bfloat16 g_Alo[(size_t)BDIM * KDIM];
__device__ __align__(256) __nv_bfloat16 g_Whi[(size_t)NDIM * KDIM];
__device__ __align__(256) __nv_bfloat16 g_Wlo[(size_t)NDIM * KDIM];
__device__ __align__(256) float         g_bias[NDIM];   // interleaved j*4+g
__device__ __align__(256) float         g_mask[BDIM];

// ===================== small PTX helpers (sm_80+ features only) =====================
__device__ __forceinline__ uint32_t smem_to_u32(const void* p) {
    uint32_t a;
    asm("{ .reg .u64 t; cvta.to.shared.u64 t, %1; cvt.u32.u64 %0, t; }" : "=r"(a) : "l"(p));
    return a;
}

__device__ __forceinline__ void cp16(uint32_t saddr, const void* g) {
    asm volatile("cp.async.cg.shared.global [%0], [%1], 16;" :: "r"(saddr), "l"(g) : "memory");
}

#define CP_COMMIT() asm volatile("cp.async.commit_group;" ::: "memory")
#define CP_WAIT(N)  asm volatile("cp.async.wait_group %0;" :: "n"(N) : "memory")

__device__ __forceinline__ void ldsm4(uint32_t* r, uint32_t addr) {
    asm volatile("ldmatrix.sync.aligned.m8n8.x4.shared.b16 {%0,%1,%2,%3}, [%4];"
                 : "=r"(r[0]), "=r"(r[1]), "=r"(r[2]), "=r"(r[3]) : "r"(addr));
}

__device__ __forceinline__ void mma16816(float* c, const uint32_t* a, uint32_t b0, uint32_t b1) {
    asm volatile(
        "mma.sync.aligned.m16n8k16.row.col.f32.bf16.bf16.f32 "
        "{%0,%1,%2,%3}, {%4,%5,%6,%7}, {%8,%9}, {%0,%1,%2,%3};"
        : "+f"(c[0]), "+f"(c[1]), "+f"(c[2]), "+f"(c[3])
        : "r"(a[0]), "r"(a[1]), "r"(a[2]), "r"(a[3]), "r"(b0), "r"(b1));
}

// ===================== split-bf16 helpers =====================
__device__ __forceinline__ uint32_t pk2(__nv_bfloat16 a, __nv_bfloat16 b) {
    __nv_bfloat162 t = __halves2bfloat162(a, b);
    return *reinterpret_cast<uint32_t*>(&t);
}

__device__ __forceinline__ float split_store4(float4 v, __nv_bfloat16* hip, __nv_bfloat16* lop) {
    __nv_bfloat16 h0 = __float2bfloat16(v.x), h1 = __float2bfloat16(v.y),
                  h2 = __float2bfloat16(v.z), h3 = __float2bfloat16(v.w);
    float l0 = v.x - __bfloat162float(h0), l1 = v.y - __bfloat162float(h1),
          l2 = v.z - __bfloat162float(h2), l3 = v.w - __bfloat162float(h3);
    uint2 hv = make_uint2(pk2(h0, h1), pk2(h2, h3));
    uint2 lv = make_uint2(pk2(__float2bfloat16(l0), __float2bfloat16(l1)),
                          pk2(__float2bfloat16(l2), __float2bfloat16(l3)));
    *reinterpret_cast<uint2*>(hip) = hv;
    *reinterpret_cast<uint2*>(lop) = lv;
    return v.x * v.x + v.y * v.y + v.z * v.z + v.w * v.w;
}

// ===================== kernel 1: convert A = [x | h_prev] + silence mask =====================
__global__ void convert_A_kernel(const float* __restrict__ x, const float* __restrict__ h) {
    int m = blockIdx.x;
    int t = threadIdx.x;  // 256
    float4 vx = reinterpret_cast<const float4*>(x)[(size_t)m * 256 + t];
    float ss = split_store4(vx, g_Ahi + (size_t)m * KDIM + 4 * t,
                                g_Alo + (size_t)m * KDIM + 4 * t);
    float4 vh = reinterpret_cast<const float4*>(h)[(size_t)m * 256 + t];
    split_store4(vh, g_Ahi + (size_t)m * KDIM + IDIM + 4 * t,
                     g_Alo + (size_t)m * KDIM + IDIM + 4 * t);

    __shared__ float red[256];
    red[t] = ss;
    __syncthreads();
    for (int s = 128; s > 0; s >>= 1) {
        if (t < s) red[t] += red[t + s];
        __syncthreads();
    }
    if (t == 0) g_mask[m] = (red[0] > 1e-6f) ? 1.0f : 0.0f;  // norm > 0.001
}

// ===================== kernel 2: convert packed weights (interleaved rows) =====================
__global__ void convert_W_kernel(const float* __restrict__ Wf, const float* __restrict__ Wi,
                                 const float* __restrict__ Wo, const float* __restrict__ Wc,
                                 const float* __restrict__ Vf, const float* __restrict__ Vi,
                                 const float* __restrict__ Vo, const float* __restrict__ Vc) {
    int n = blockIdx.x;     // 0..4095 (gate-major source index)
    int t = threadIdx.x;    // 256
    int g = n >> 10, j = n & 1023;
    int row = (j << 2) | g;  // interleaved destination row
    const float* W = (g == 0) ? Wf : (g == 1) ? Wi : (g == 2) ? Wo : Wc;
    const float* V = (g == 0) ? Vf : (g == 1) ? Vi : (g == 2) ? Vo : Vc;
    float4 vw = reinterpret_cast<const float4*>(W)[(size_t)j * 256 + t];
    split_store4(vw, g_Whi + (size_t)row * KDIM + 4 * t,
                     g_Wlo + (size_t)row * KDIM + 4 * t);
    float4 vv = reinterpret_cast<const float4*>(V)[(size_t)j * 256 + t];
    split_store4(vv, g_Whi + (size_t)row * KDIM + IDIM + 4 * t,
                     g_Wlo + (size_t)row * KDIM + IDIM + 4 * t);
}

// ===================== kernel 3: combined bias (interleaved) =====================
__global__ void bias_kernel(const float* __restrict__ bWf, const float* __restrict__ bVf, const float* __restrict__ bf_,
                            const float* __restrict__ bWi, const float* __restrict__ bVi, const float* __restrict__ bi_,
                            const float* __restrict__ bWo, const float* __restrict__ bVo, const float* __restrict__ bo_,
                            const float* __restrict__ bWc, const float* __restrict__ bVc, const float* __restrict__ bc_) {
    int n = blockIdx.x * blockDim.x + threadIdx.x;
    if (n >= NDIM) return;
    int g = n >> 10, j = n & 1023;
    const float* a = (g == 0) ? bWf : (g == 1) ? bWi : (g == 2) ? bWo : bWc;
    const float* b = (g == 0) ? bVf : (g == 1) ? bVi : (g == 2) ? bVo : bVc;
    const float* c = (g == 0) ? bf_ : (g == 1) ? bi_ : (g == 2) ? bo_ : bc_;
    g_bias[(j << 2) | g] = a[j] + b[j] + c[j];
}

// ===================== kernel 4: pipelined GEMM + fused LSTM epilogue =====================
// gates = Ahi*Whi^T + Ahi*Wlo^T + Alo*Whi^T  (fp32 accum), then activations -> out
#define BM 128
#define BN 128
#define BK 32
#define NK (KDIM / BK)          // 64 k-tiles
#define NTILES 32               // tiles per dim
#define TOTAL_TILES 1024
#define GRID_CTAS 888           // 3 * 296; bids < 136 do 2 tiles
#define BUF_BYTES (128 * 64)    // 8192: 128 rows x 64B (pitch 64, swizzled)
#define STAGE_BYTES (4 * BUF_BYTES)    // 32768: Ahi, Alo, Whi, Wlo
#define NSTAGES 3
#define GEMM_SMEM (NSTAGES * STAGE_BYTES)  // 98304
#define EPITCH 132              // floats per gates row in smem epilogue

// swizzled byte offset of 16B chunk c (0..3) in row r, pitch 64
__device__ __forceinline__ uint32_t swz(int r, int c) {
    return (uint32_t)(r * 64 + ((c ^ ((r >> 1) & 3)) << 4));
}

__device__ __forceinline__ void load_stage(uint32_t sb, int stage, int kt, int tid,
                                           const __nv_bfloat16* Ahi, const __nv_bfloat16* Alo,
                                           const __nv_bfloat16* Whi, const __nv_bfloat16* Wlo) {
    uint32_t s0 = sb + (uint32_t)stage * STAGE_BYTES;
    #pragma unroll
    for (int i = 0; i < 2; ++i) {
        int q = tid + i * 256;
        int r = q >> 2, c = q & 3;                    // row 0..127, 16B chunk 0..3
        size_t goff = (size_t)r * KDIM + (size_t)kt * BK + c * 8;
        uint32_t soff = swz(r, c);
        cp16(s0 + soff,                 Ahi + goff);
        cp16(s0 + BUF_BYTES + soff,     Alo + goff);
        cp16(s0 + 2 * BUF_BYTES + soff, Whi + goff);
        cp16(s0 + 3 * BUF_BYTES + soff, Wlo + goff);
    }
    CP_COMMIT();
}

__global__ void __launch_bounds__(256, 2) gemm_kernel(const float* __restrict__ c_prev,
                                                      float* __restrict__ out, int n_out) {
    extern __shared__ char smem[];
    uint32_t sb = smem_to_u32(smem);
    int tid = threadIdx.x, wid = tid >> 5, lid = tid & 31;
    int wm = (wid >> 1) * 32;   // 4x2 warp grid, warp tile 32x64
    int wn = (wid & 1) * 64;
    int lrow = lid & 15;
    int cbase = lid >> 4;       // 0 or 1: second 16B chunk within k-step

    for (int t = blockIdx.x; t < TOTAL_TILES; t += GRID_CTAS) {
        int m0 = (t >> 5) * BM;
        int n0 = (t & 31) * BN;
        int j_base = n0 >> 2;   // interleaved: 32 j's per CTA tile

        const __nv_bfloat16* Ahi = g_Ahi + (size_t)m0 * KDIM;
        const __nv_bfloat16* Alo = g_Alo + (size_t)m0 * KDIM;
        const __nv_bfloat16* Whi = g_Whi + (size_t)n0 * KDIM;
        const __nv_bfloat16* Wlo = g_Wlo + (size_t)n0 * KDIM;

        float acc[2][8][4];
        #pragma unroll
        for (int i = 0; i < 2; ++i)
            #pragma unroll
            for (int j = 0; j < 8; ++j)
                #pragma unroll
                for (int k = 0; k < 4; ++k) acc[i][j][k] = 0.0f;

        // prologue: stages 0,1
        load_stage(sb, 0, 0, tid, Ahi, Alo, Whi, Wlo);
        load_stage(sb, 1, 1, tid, Ahi, Alo, Whi, Wlo);

        for (int kt = 0; kt < NK; ++kt) {
            if (kt < NK - 1) { CP_WAIT(1); } else { CP_WAIT(0); }
            __syncthreads();   // tile kt visible to all; frees buffer (kt+2)%3

            uint32_t cur = sb + (uint32_t)(kt % NSTAGES) * STAGE_BYTES;
            uint32_t sAhi = cur;
            uint32_t sAlo = cur + BUF_BYTES;
            uint32_t sWhi = cur + 2 * BUF_BYTES;
            uint32_t sWlo = cur + 3 * BUF_BYTES;

            #pragma unroll
            for (int ks = 0; ks < 2; ++ks) {
                int cidx = ks * 2 + cbase;   // 16B chunk index 0..3

                uint32_t ahi[2][4], w0[4][4];
                #pragma unroll
                for (int am = 0; am < 2; ++am)
                    ldsm4(ahi[am], sAhi + swz(wm + am * 16 + lrow, cidx));
                #pragma unroll
                for (int bn = 0; bn < 4; ++bn)
                    ldsm4(w0[bn], sWhi + swz(wn + bn * 16 + lrow, cidx));

                // pass 1: Ahi * Whi
                #pragma unroll
                for (int am = 0; am < 2; ++am)
                    #pragma unroll
                    for (int bn = 0; bn < 4; ++bn) {
                        mma16816(acc[am][2 * bn],     ahi[am], w0[bn][0], w0[bn][2]);
                        mma16816(acc[am][2 * bn + 1], ahi[am], w0[bn][1], w0[bn][3]);
                    }

                // pass 2: Ahi * Wlo
                uint32_t w1[4][4];
                #pragma unroll
                for (int bn = 0; bn < 4; ++bn)
                    ldsm4(w1[bn], sWlo + swz(wn + bn * 16 + lrow, cidx));
                #pragma unroll
                for (int am = 0; am < 2; ++am)
                    #pragma unroll
                    for (int bn = 0; bn < 4; ++bn) {
                        mma16816(acc[am][2 * bn],     ahi[am], w1[bn][0], w1[bn][2]);
                        mma16816(acc[am][2 * bn + 1], ahi[am], w1[bn][1], w1[bn][3]);
                    }

                // pass 3: Alo * Whi
                uint32_t alo[2][4];
                #pragma unroll
                for (int am = 0; am < 2; ++am)
                    ldsm4(alo[am], sAlo + swz(wm + am * 16 + lrow, cidx));
                #pragma unroll
                for (int am = 0; am < 2; ++am)
                    #pragma unroll
                    for (int bn = 0; bn < 4; ++bn) {
                        mma16816(acc[am][2 * bn],     alo[am], w0[bn][0], w0[bn][2]);
                        mma16816(acc[am][2 * bn + 1], alo[am], w0[bn][1], w0[bn][3]);
                    }
            }

            // prefetch tile kt+2 (top barrier of next iter protects WAR)
            if (kt + 2 < NK)
                load_stage(sb, (kt + 2) % NSTAGES, kt + 2, tid, Ahi, Alo, Whi, Wlo);
        }

        // ===== fused epilogue: acc -> smem -> activations -> out =====
        __syncthreads();   // done reading stage buffers; reuse smem for gates
        float* sg = reinterpret_cast<float*>(smem);   // [128][EPITCH]
        int gid = lid >> 2, tig = lid & 3;
        #pragma unroll
        for (int am = 0; am < 2; ++am) {
            #pragma unroll
            for (int bn = 0; bn < 8; ++bn) {
                const float* c = acc[am][bn];
                int row = wm + am * 16 + gid;
                int col = wn + bn * 8 + tig * 2;
                sg[row * EPITCH + col]           = c[0];
                sg[row * EPITCH + col + 1]       = c[1];
                sg[(row + 8) * EPITCH + col]     = c[2];
                sg[(row + 8) * EPITCH + col + 1] = c[3];
            }
        }
        __syncthreads();

        const int BH = BDIM * HDIM;
        #pragma unroll
        for (int i = 0; i < 16; ++i) {
            int idx = tid + i * 256;       // 128 rows x 32 j
            int row = idx >> 5, lj = idx & 31;
            float4 gv = *reinterpret_cast<const float4*>(&sg[row * EPITCH + lj * 4]);
            int jg = j_base + lj;
            float4 bv = *reinterpret_cast<const float4*>(&g_bias[jg * 4]);
            float fp = gv.x + bv.x, ip = gv.y + bv.y, op = gv.z + bv.z, cp = gv.w + bv.w;
            float ft = 1.0f / (1.0f + expf(-fp));
            float it = 1.0f / (1.0f + expf(-ip));
            float ot = 1.0f / (1.0f + expf(-op));
            float ct = tanhf(cp);
            int m = m0 + row;
            int oidx = m * HDIM + jg;
            float cpv = c_prev[oidx];
            float cn = ft * cpv + it * cpv + g_mask[m] * (it * ct);
            float hn = ot * tanhf(cn);
            out[oidx] = hn;
            if (BH + oidx < n_out)     out[BH + oidx] = cn;
            if (2 * BH + oidx < n_out) out[2 * BH + oidx] = ct;
        }
        __syncthreads();   // epilogue reads done before next tile's cp.async writes
    }
}

// ===================== launcher =====================
extern "C" void kernel_launch(void* const* d_in, const int* in_sizes, int n_in,
                              void* d_out, int out_size) {
    (void)n_in;
    const float* x      = (const float*)d_in[0];
    const float* h_prev = (const float*)d_in[1];
    const float* c_prev = (const float*)d_in[2];
    // d_in[3] = c_prev_tilde_dummy (unused)

    // Input order detection (dict order vs signature order); see round-2 notes.
    const float *W[4], *V[4], *bW[4], *bV[4], *bx[4];
    if (in_sizes[8] > 100000) {
        for (int g = 0; g < 4; ++g) {   // dict order
            W[g]  = (const float*)d_in[4 + 4 * g];
            bW[g] = (const float*)d_in[5 + 4 * g];
            V[g]  = (const float*)d_in[6 + 4 * g];
            bV[g] = (const float*)d_in[7 + 4 * g];
            bx[g] = (const float*)d_in[20 + g];
        }
    } else {
        for (int g = 0; g < 4; ++g) {   // signature order
            W[g]  = (const float*)d_in[4 + 5 * g];
            bW[g] = (const float*)d_in[5 + 5 * g];
            V[g]  = (const float*)d_in[6 + 5 * g];
            bV[g] = (const float*)d_in[7 + 5 * g];
            bx[g] = (const float*)d_in[8 + 5 * g];
        }
    }

    convert_A_kernel<<<BDIM, 256>>>(x, h_prev);
    convert_W_kernel<<<NDIM, 256>>>(W[0], W[1], W[2], W[3], V[0], V[1], V[2], V[3]);
    bias_kernel<<<NDIM / 256, 256>>>(bW[0], bV[0], bx[0], bW[1], bV[1], bx[1],
                                     bW[2], bV[2], bx[2], bW[3], bV[3], bx[3]);

    static bool attr_set = false;
    if (!attr_set) {
        cudaFuncSetAttribute(gemm_kernel, cudaFuncAttributeMaxDynamicSharedMemorySize,
                             (int)GEMM_SMEM);
        attr_set = true;
    }
    gemm_kernel<<<GRID_CTAS, 256, GEMM_SMEM>>>(c_prev, (float*)d_out, out_size);
}

// round 6
// speedup vs baseline: 1.2945x; 1.0114x over previous
#include <cuda_runtime.h>
#include <cuda_bf16.h>
#include <cstdint>

// ===================== problem dims =====================
#define BDIM 4096
#define IDIM 1024
#define HDIM 1024
#define KDIM 2048   // I + H
#define NDIM 4096   // 4 * H, INTERLEAVED: n = j*4 + g  (g in {f,i,o,c})

// ===================== device scratch (static, allowed) =====================
__device__ __align__(256) __nv_bfloat16 g_Ahi[(size_t)BDIM * KDIM];
__device__ __align__(256) __nv_bfloat16 g_Alo[(size_t)BDIM * KDIM];
__device__ __align__(256) __nv_bfloat16 g_Whi[(size_t)NDIM * KDIM];
__device__ __align__(256) __nv_bfloat16 g_Wlo[(size_t)NDIM * KDIM];
__device__ __align__(256) float         g_bias[NDIM];   // interleaved j*4+g
__device__ __align__(256) float         g_mask[BDIM];

// ===================== small PTX helpers (sm_80+ features only) =====================
__device__ __forceinline__ uint32_t smem_to_u32(const void* p) {
    uint32_t a;
    asm("{ .reg .u64 t; cvta.to.shared.u64 t, %1; cvt.u32.u64 %0, t; }" : "=r"(a) : "l"(p));
    return a;
}

__device__ __forceinline__ void cp16(uint32_t saddr, const void* g) {
    asm volatile("cp.async.cg.shared.global [%0], [%1], 16;" :: "r"(saddr), "l"(g) : "memory");
}

#define CP_COMMIT() asm volatile("cp.async.commit_group;" ::: "memory")
#define CP_WAIT(N)  asm volatile("cp.async.wait_group %0;" :: "n"(N) : "memory")

__device__ __forceinline__ void ldsm4(uint32_t* r, uint32_t addr) {
    asm volatile("ldmatrix.sync.aligned.m8n8.x4.shared.b16 {%0,%1,%2,%3}, [%4];"
                 : "=r"(r[0]), "=r"(r[1]), "=r"(r[2]), "=r"(r[3]) : "r"(addr));
}

__device__ __forceinline__ void mma16816(float* c, const uint32_t* a, uint32_t b0, uint32_t b1) {
    asm volatile(
        "mma.sync.aligned.m16n8k16.row.col.f32.bf16.bf16.f32 "
        "{%0,%1,%2,%3}, {%4,%5,%6,%7}, {%8,%9}, {%0,%1,%2,%3};"
        : "+f"(c[0]), "+f"(c[1]), "+f"(c[2]), "+f"(c[3])
        : "r"(a[0]), "r"(a[1]), "r"(a[2]), "r"(a[3]), "r"(b0), "r"(b1));
}

// ===================== split-bf16 helpers =====================
__device__ __forceinline__ uint32_t pk2(__nv_bfloat16 a, __nv_bfloat16 b) {
    __nv_bfloat162 t = __halves2bfloat162(a, b);
    return *reinterpret_cast<uint32_t*>(&t);
}

__device__ __forceinline__ float split_store4(float4 v, __nv_bfloat16* hip, __nv_bfloat16* lop) {
    __nv_bfloat16 h0 = __float2bfloat16(v.x), h1 = __float2bfloat16(v.y),
                  h2 = __float2bfloat16(v.z), h3 = __float2bfloat16(v.w);
    float l0 = v.x - __bfloat162float(h0), l1 = v.y - __bfloat162float(h1),
          l2 = v.z - __bfloat162float(h2), l3 = v.w - __bfloat162float(h3);
    uint2 hv = make_uint2(pk2(h0, h1), pk2(h2, h3));
    uint2 lv = make_uint2(pk2(__float2bfloat16(l0), __float2bfloat16(l1)),
                          pk2(__float2bfloat16(l2), __float2bfloat16(l3)));
    *reinterpret_cast<uint2*>(hip) = hv;
    *reinterpret_cast<uint2*>(lop) = lv;
    return v.x * v.x + v.y * v.y + v.z * v.z + v.w * v.w;
}

// ===================== kernel 1: convert A = [x | h_prev] + silence mask =====================
__global__ void convert_A_kernel(const float* __restrict__ x, const float* __restrict__ h) {
    int m = blockIdx.x;
    int t = threadIdx.x;  // 256
    float4 vx = reinterpret_cast<const float4*>(x)[(size_t)m * 256 + t];
    float ss = split_store4(vx, g_Ahi + (size_t)m * KDIM + 4 * t,
                                g_Alo + (size_t)m * KDIM + 4 * t);
    float4 vh = reinterpret_cast<const float4*>(h)[(size_t)m * 256 + t];
    split_store4(vh, g_Ahi + (size_t)m * KDIM + IDIM + 4 * t,
                     g_Alo + (size_t)m * KDIM + IDIM + 4 * t);

    __shared__ float red[256];
    red[t] = ss;
    __syncthreads();
    for (int s = 128; s > 0; s >>= 1) {
        if (t < s) red[t] += red[t + s];
        __syncthreads();
    }
    if (t == 0) g_mask[m] = (red[0] > 1e-6f) ? 1.0f : 0.0f;  // norm > 0.001
}

// ===================== kernel 2: convert packed weights (interleaved rows) =====================
__global__ void convert_W_kernel(const float* __restrict__ Wf, const float* __restrict__ Wi,
                                 const float* __restrict__ Wo, const float* __restrict__ Wc,
                                 const float* __restrict__ Vf, const float* __restrict__ Vi,
                                 const float* __restrict__ Vo, const float* __restrict__ Vc) {
    int n = blockIdx.x;     // 0..4095 (gate-major source index)
    int t = threadIdx.x;    // 256
    int g = n >> 10, j = n & 1023;
    int row = (j << 2) | g;  // interleaved destination row
    const float* W = (g == 0) ? Wf : (g == 1) ? Wi : (g == 2) ? Wo : Wc;
    const float* V = (g == 0) ? Vf : (g == 1) ? Vi : (g == 2) ? Vo : Vc;
    float4 vw = reinterpret_cast<const float4*>(W)[(size_t)j * 256 + t];
    split_store4(vw, g_Whi + (size_t)row * KDIM + 4 * t,
                     g_Wlo + (size_t)row * KDIM + 4 * t);
    float4 vv = reinterpret_cast<const float4*>(V)[(size_t)j * 256 + t];
    split_store4(vv, g_Whi + (size_t)row * KDIM + IDIM + 4 * t,
                     g_Wlo + (size_t)row * KDIM + IDIM + 4 * t);
}

// ===================== kernel 3: combined bias (interleaved) =====================
__global__ void bias_kernel(const float* __restrict__ bWf, const float* __restrict__ bVf, const float* __restrict__ bf_,
                            const float* __restrict__ bWi, const float* __restrict__ bVi, const float* __restrict__ bi_,
                            const float* __restrict__ bWo, const float* __restrict__ bVo, const float* __restrict__ bo_,
                            const float* __restrict__ bWc, const float* __restrict__ bVc, const float* __restrict__ bc_) {
    int n = blockIdx.x * blockDim.x + threadIdx.x;
    if (n >= NDIM) return;
    int g = n >> 10, j = n & 1023;
    const float* a = (g == 0) ? bWf : (g == 1) ? bWi : (g == 2) ? bWo : bWc;
    const float* b = (g == 0) ? bVf : (g == 1) ? bVi : (g == 2) ? bVo : bVc;
    const float* c = (g == 0) ? bf_ : (g == 1) ? bi_ : (g == 2) ? bo_ : bc_;
    g_bias[(j << 2) | g] = a[j] + b[j] + c[j];
}

// ===================== kernel 4: pipelined GEMM + fused LSTM epilogue =====================
// gates = Ahi*Whi^T + Ahi*Wlo^T + Alo*Whi^T  (fp32 accum), then activations -> out
#define BM 128
#define BN 128
#define BK 32
#define NK (KDIM / BK)          // 64 k-tiles
#define TOTAL_TILES 1024
#define GRID_CTAS 888           // 3 * 296; 136 CTAs do 2 tiles
#define BUF_BYTES (128 * 64)    // 8192: 128 rows x 64B (pitch 64, swizzled)
#define STAGE_BYTES (4 * BUF_BYTES)    // 32768: Ahi, Alo, Whi, Wlo
#define NSTAGES 3
#define GEMM_SMEM (NSTAGES * STAGE_BYTES)  // 98304
#define EPITCH 132              // floats per gates row in smem epilogue

// swizzled byte offset of 16B chunk c (0..3) in row r, pitch 64.
// NOTE: swz(r+16, c) == swz(r, c) + 1024  (the swizzle term (r>>1)&3 is
// invariant under r += 16), so per-fragment offsets are immediates.
__device__ __forceinline__ uint32_t swz(int r, int c) {
    return (uint32_t)(r * 64 + ((c ^ ((r >> 1) & 3)) << 4));
}

__global__ void __launch_bounds__(256, 2) gemm_kernel(const float* __restrict__ c_prev,
                                                      float* __restrict__ out, int n_out) {
    extern __shared__ char smem[];
    uint32_t sb = smem_to_u32(smem);
    int tid = threadIdx.x, wid = tid >> 5, lid = tid & 31;
    int wm = (wid >> 1) * 32;   // 4x2 warp grid, warp tile 32x64
    int wn = (wid & 1) * 64;
    int lrow = lid & 31 & 15;
    int cbase = lid >> 4;       // 0 or 1: second 16B chunk within k-step

    // ---- thread-invariant ldmatrix base offsets (all other addrs = these + immediates)
    uint32_t offA0[2], offW0[2];
    #pragma unroll
    for (int ks = 0; ks < 2; ++ks) {
        int cidx = ks * 2 + cbase;
        offA0[ks] = swz(wm + lrow, cidx);
        offW0[ks] = swz(wn + lrow, cidx) + 2u * BUF_BYTES;  // W buffers sit after A buffers
    }

    // ---- thread-invariant cp.async producer offsets
    int ls_r0 = tid >> 2, ls_c0 = tid & 3;            // q = tid
    int ls_r1 = (tid + 256) >> 2;                     // q = tid + 256 (same c)
    uint32_t ls_soff0 = swz(ls_r0, ls_c0);
    uint32_t ls_soff1 = swz(ls_r1, ls_c0);
    size_t ls_goff0 = (size_t)ls_r0 * KDIM + ls_c0 * 8;
    size_t ls_goff1 = (size_t)ls_r1 * KDIM + ls_c0 * 8;

    for (int t = blockIdx.x; t < TOTAL_TILES; t += GRID_CTAS) {
        int m0 = (t >> 5) * BM;
        int n0 = (t & 31) * BN;
        int j_base = n0 >> 2;   // interleaved: 32 j's per CTA tile

        const __nv_bfloat16* Ahi = g_Ahi + (size_t)m0 * KDIM;
        const __nv_bfloat16* Alo = g_Alo + (size_t)m0 * KDIM;
        const __nv_bfloat16* Whi = g_Whi + (size_t)n0 * KDIM;
        const __nv_bfloat16* Wlo = g_Wlo + (size_t)n0 * KDIM;

        // per-tile producer pointers (advance by BK per stage load)
        const __nv_bfloat16* pAhi0 = Ahi + ls_goff0;
        const __nv_bfloat16* pAhi1 = Ahi + ls_goff1;
        const __nv_bfloat16* pAlo0 = Alo + ls_goff0;
        const __nv_bfloat16* pAlo1 = Alo + ls_goff1;
        const __nv_bfloat16* pWhi0 = Whi + ls_goff0;
        const __nv_bfloat16* pWhi1 = Whi + ls_goff1;
        const __nv_bfloat16* pWlo0 = Wlo + ls_goff0;
        const __nv_bfloat16* pWlo1 = Wlo + ls_goff1;

        #define LOAD_STAGE(stage, kt) do {                                      \
            uint32_t s0_ = sb + (uint32_t)(stage) * STAGE_BYTES;                \
            int ko_ = (kt) * BK;                                                \
            cp16(s0_ + ls_soff0,                 pAhi0 + ko_);                  \
            cp16(s0_ + ls_soff1,                 pAhi1 + ko_);                  \
            cp16(s0_ + BUF_BYTES + ls_soff0,     pAlo0 + ko_);                  \
            cp16(s0_ + BUF_BYTES + ls_soff1,     pAlo1 + ko_);                  \
            cp16(s0_ + 2 * BUF_BYTES + ls_soff0, pWhi0 + ko_);                  \
            cp16(s0_ + 2 * BUF_BYTES + ls_soff1, pWhi1 + ko_);                  \
            cp16(s0_ + 3 * BUF_BYTES + ls_soff0, pWlo0 + ko_);                  \
            cp16(s0_ + 3 * BUF_BYTES + ls_soff1, pWlo1 + ko_);                  \
            CP_COMMIT();                                                        \
        } while (0)

        float acc[2][8][4];
        #pragma unroll
        for (int i = 0; i < 2; ++i)
            #pragma unroll
            for (int j = 0; j < 8; ++j)
                #pragma unroll
                for (int k = 0; k < 4; ++k) acc[i][j][k] = 0.0f;

        // prologue: stages 0,1
        LOAD_STAGE(0, 0);
        LOAD_STAGE(1, 1);

        for (int kt = 0; kt < NK; ++kt) {
            if (kt < NK - 1) { CP_WAIT(1); } else { CP_WAIT(0); }
            __syncthreads();   // tile kt visible to all; frees buffer (kt+2)%3

            uint32_t cur = sb + (uint32_t)(kt % NSTAGES) * STAGE_BYTES;

            #pragma unroll
            for (int ks = 0; ks < 2; ++ks) {
                uint32_t aB = cur + offA0[ks];   // Ahi fragment base
                uint32_t wB = cur + offW0[ks];   // Whi fragment base

                uint32_t ahi[2][4], w0[4][4];
                ldsm4(ahi[0], aB);
                ldsm4(ahi[1], aB + 1024u);
                #pragma unroll
                for (int bn = 0; bn < 4; ++bn)
                    ldsm4(w0[bn], wB + (uint32_t)(bn * 1024));

                // pass 1: Ahi * Whi
                #pragma unroll
                for (int am = 0; am < 2; ++am)
                    #pragma unroll
                    for (int bn = 0; bn < 4; ++bn) {
                        mma16816(acc[am][2 * bn],     ahi[am], w0[bn][0], w0[bn][2]);
                        mma16816(acc[am][2 * bn + 1], ahi[am], w0[bn][1], w0[bn][3]);
                    }

                // pass 2: Ahi * Wlo  (Wlo buffer = Whi buffer + BUF_BYTES)
                uint32_t w1[4][4];
                #pragma unroll
                for (int bn = 0; bn < 4; ++bn)
                    ldsm4(w1[bn], wB + (uint32_t)(BUF_BYTES + bn * 1024));
                #pragma unroll
                for (int am = 0; am < 2; ++am)
                    #pragma unroll
                    for (int bn = 0; bn < 4; ++bn) {
                        mma16816(acc[am][2 * bn],     ahi[am], w1[bn][0], w1[bn][2]);
                        mma16816(acc[am][2 * bn + 1], ahi[am], w1[bn][1], w1[bn][3]);
                    }

                // pass 3: Alo * Whi  (Alo buffer = Ahi buffer + BUF_BYTES)
                uint32_t alo[2][4];
                ldsm4(alo[0], aB + (uint32_t)BUF_BYTES);
                ldsm4(alo[1], aB + (uint32_t)(BUF_BYTES + 1024));
                #pragma unroll
                for (int am = 0; am < 2; ++am)
                    #pragma unroll
                    for (int bn = 0; bn < 4; ++bn) {
                        mma16816(acc[am][2 * bn],     alo[am], w0[bn][0], w0[bn][2]);
                        mma16816(acc[am][2 * bn + 1], alo[am], w0[bn][1], w0[bn][3]);
                    }
            }

            // prefetch tile kt+2 (top barrier of next iter protects WAR)
            if (kt + 2 < NK)
                LOAD_STAGE((kt + 2) % NSTAGES, kt + 2);
        }
        #undef LOAD_STAGE

        // ===== fused epilogue: acc -> smem -> activations -> out =====
        __syncthreads();   // done reading stage buffers; reuse smem for gates
        float* sg = reinterpret_cast<float*>(smem);   // [128][EPITCH]
        int gid = lid >> 2, tig = lid & 3;
        #pragma unroll
        for (int am = 0; am < 2; ++am) {
            #pragma unroll
            for (int bn = 0; bn < 8; ++bn) {
                const float* c = acc[am][bn];
                int row = wm + am * 16 + gid;
                int col = wn + bn * 8 + tig * 2;
                sg[row * EPITCH + col]           = c[0];
                sg[row * EPITCH + col + 1]       = c[1];
                sg[(row + 8) * EPITCH + col]     = c[2];
                sg[(row + 8) * EPITCH + col + 1] = c[3];
            }
        }
        __syncthreads();

        const int BH = BDIM * HDIM;
        #pragma unroll
        for (int i = 0; i < 16; ++i) {
            int idx = tid + i * 256;       // 128 rows x 32 j
            int row = idx >> 5, lj = idx & 31;
            float4 gv = *reinterpret_cast<const float4*>(&sg[row * EPITCH + lj * 4]);
            int jg = j_base + lj;
            float4 bv = *reinterpret_cast<const float4*>(&g_bias[jg * 4]);
            float fp = gv.x + bv.x, ip = gv.y + bv.y, op = gv.z + bv.z, cp = gv.w + bv.w;
            float ft = 1.0f / (1.0f + expf(-fp));
            float it = 1.0f / (1.0f + expf(-ip));
            float ot = 1.0f / (1.0f + expf(-op));
            float ct = tanhf(cp);
            int m = m0 + row;
            int oidx = m * HDIM + jg;
            float cpv = c_prev[oidx];
            float cn = ft * cpv + it * cpv + g_mask[m] * (it * ct);
            float hn = ot * tanhf(cn);
            out[oidx] = hn;
            if (BH + oidx < n_out)     out[BH + oidx] = cn;
            if (2 * BH + oidx < n_out) out[2 * BH + oidx] = ct;
        }
        __syncthreads();   // epilogue reads done before next tile's cp.async writes
    }
}

// ===================== launcher =====================
extern "C" void kernel_launch(void* const* d_in, const int* in_sizes, int n_in,
                              void* d_out, int out_size) {
    (void)n_in;
    const float* x      = (const float*)d_in[0];
    const float* h_prev = (const float*)d_in[1];
    const float* c_prev = (const float*)d_in[2];
    // d_in[3] = c_prev_tilde_dummy (unused)

    // Input order detection (dict order vs signature order); see round-2 notes.
    const float *W[4], *V[4], *bW[4], *bV[4], *bx[4];
    if (in_sizes[8] > 100000) {
        for (int g = 0; g < 4; ++g) {   // dict order
            W[g]  = (const float*)d_in[4 + 4 * g];
            bW[g] = (const float*)d_in[5 + 4 * g];
            V[g]  = (const float*)d_in[6 + 4 * g];
            bV[g] = (const float*)d_in[7 + 4 * g];
            bx[g] = (const float*)d_in[20 + g];
        }
    } else {
        for (int g = 0; g < 4; ++g) {   // signature order
            W[g]  = (const float*)d_in[4 + 5 * g];
            bW[g] = (const float*)d_in[5 + 5 * g];
            V[g]  = (const float*)d_in[6 + 5 * g];
            bV[g] = (const float*)d_in[7 + 5 * g];
            bx[g] = (const float*)d_in[8 + 5 * g];
        }
    }

    convert_A_kernel<<<BDIM, 256>>>(x, h_prev);
    convert_W_kernel<<<NDIM, 256>>>(W[0], W[1], W[2], W[3], V[0], V[1], V[2], V[3]);
    bias_kernel<<<NDIM / 256, 256>>>(bW[0], bV[0], bx[0], bW[1], bV[1], bx[1],
                                     bW[2], bV[2], bx[2], bW[3], bV[3], bx[3]);

    static bool attr_set = false;
    if (!attr_set) {
        cudaFuncSetAttribute(gemm_kernel, cudaFuncAttributeMaxDynamicSharedMemorySize,
                             (int)GEMM_SMEM);
        attr_set = true;
    }
    gemm_kernel<<<GRID_CTAS, 256, GEMM_SMEM>>>(c_prev, (float*)d_out, out_size);
}

// round 7
// speedup vs baseline: 1.8596x; 1.4366x over previous
#include <cuda_runtime.h>
#include <cuda_fp16.h>
#include <cstdint>

// ===================== problem dims =====================
#define BDIM 4096
#define IDIM 1024
#define HDIM 1024
#define KDIM 2048   // I + H
#define NDIM 4096   // 4 * H, INTERLEAVED: n = j*4 + g  (g in {f,i,o,c})

// ===================== device scratch (static, allowed) =====================
__device__ __align__(256) __half g_A  [(size_t)BDIM * KDIM];   // fp16(x|h)
__device__ __align__(256) __half g_Whi[(size_t)NDIM * KDIM];   // fp16(W)
__device__ __align__(256) __half g_Wlo[(size_t)NDIM * KDIM];   // fp16(W - Whi)
__device__ __align__(256) float  g_bias[NDIM];                 // interleaved j*4+g
__device__ __align__(256) float  g_mask[BDIM];

// ===================== small PTX helpers (sm_80+ features only) =====================
__device__ __forceinline__ uint32_t smem_to_u32(const void* p) {
    uint32_t a;
    asm("{ .reg .u64 t; cvta.to.shared.u64 t, %1; cvt.u32.u64 %0, t; }" : "=r"(a) : "l"(p));
    return a;
}

__device__ __forceinline__ void cp16(uint32_t saddr, const void* g) {
    asm volatile("cp.async.cg.shared.global [%0], [%1], 16;" :: "r"(saddr), "l"(g) : "memory");
}

#define CP_COMMIT() asm volatile("cp.async.commit_group;" ::: "memory")
#define CP_WAIT(N)  asm volatile("cp.async.wait_group %0;" :: "n"(N) : "memory")

__device__ __forceinline__ void ldsm4(uint32_t* r, uint32_t addr) {
    asm volatile("ldmatrix.sync.aligned.m8n8.x4.shared.b16 {%0,%1,%2,%3}, [%4];"
                 : "=r"(r[0]), "=r"(r[1]), "=r"(r[2]), "=r"(r[3]) : "r"(addr));
}

__device__ __forceinline__ void mma16816(float* c, const uint32_t* a, uint32_t b0, uint32_t b1) {
    asm volatile(
        "mma.sync.aligned.m16n8k16.row.col.f32.f16.f16.f32 "
        "{%0,%1,%2,%3}, {%4,%5,%6,%7}, {%8,%9}, {%0,%1,%2,%3};"
        : "+f"(c[0]), "+f"(c[1]), "+f"(c[2]), "+f"(c[3])
        : "r"(a[0]), "r"(a[1]), "r"(a[2]), "r"(a[3]), "r"(b0), "r"(b1));
}

// ===================== conversion helpers =====================
__device__ __forceinline__ uint32_t pkh2(__half a, __half b) {
    __half2 t = __halves2half2(a, b);
    return *reinterpret_cast<uint32_t*>(&t);
}

// store 4 fp16 (single-term) and return sum of squares
__device__ __forceinline__ float h_store4(float4 v, __half* dst) {
    uint2 hv = make_uint2(pkh2(__float2half_rn(v.x), __float2half_rn(v.y)),
                          pkh2(__float2half_rn(v.z), __float2half_rn(v.w)));
    *reinterpret_cast<uint2*>(dst) = hv;
    return v.x * v.x + v.y * v.y + v.z * v.z + v.w * v.w;
}

// split float4 into fp16 hi + fp16 lo
__device__ __forceinline__ void hsplit_store4(float4 v, __half* hip, __half* lop) {
    __half h0 = __float2half_rn(v.x), h1 = __float2half_rn(v.y),
           h2 = __float2half_rn(v.z), h3 = __float2half_rn(v.w);
    float l0 = v.x - __half2float(h0), l1 = v.y - __half2float(h1),
          l2 = v.z - __half2float(h2), l3 = v.w - __half2float(h3);
    *reinterpret_cast<uint2*>(hip) = make_uint2(pkh2(h0, h1), pkh2(h2, h3));
    *reinterpret_cast<uint2*>(lop) =
        make_uint2(pkh2(__float2half_rn(l0), __float2half_rn(l1)),
                   pkh2(__float2half_rn(l2), __float2half_rn(l3)));
}

// ===================== kernel 1: convert A = [x | h_prev] + silence mask =====================
__global__ void convert_A_kernel(const float* __restrict__ x, const float* __restrict__ h) {
    int m = blockIdx.x;
    int t = threadIdx.x;  // 256
    float4 vx = reinterpret_cast<const float4*>(x)[(size_t)m * 256 + t];
    float ss = h_store4(vx, g_A + (size_t)m * KDIM + 4 * t);
    float4 vh = reinterpret_cast<const float4*>(h)[(size_t)m * 256 + t];
    h_store4(vh, g_A + (size_t)m * KDIM + IDIM + 4 * t);

    __shared__ float red[256];
    red[t] = ss;
    __syncthreads();
    for (int s = 128; s > 0; s >>= 1) {
        if (t < s) red[t] += red[t + s];
        __syncthreads();
    }
    if (t == 0) g_mask[m] = (red[0] > 1e-6f) ? 1.0f : 0.0f;  // norm > 0.001
}

// ===================== kernel 2: convert packed weights (interleaved rows, fp16 split) ==========
__global__ void convert_W_kernel(const float* __restrict__ Wf, const float* __restrict__ Wi,
                                 const float* __restrict__ Wo, const float* __restrict__ Wc,
                                 const float* __restrict__ Vf, const float* __restrict__ Vi,
                                 const float* __restrict__ Vo, const float* __restrict__ Vc) {
    int n = blockIdx.x;     // 0..4095 (gate-major source index)
    int t = threadIdx.x;    // 256
    int g = n >> 10, j = n & 1023;
    int row = (j << 2) | g;  // interleaved destination row
    const float* W = (g == 0) ? Wf : (g == 1) ? Wi : (g == 2) ? Wo : Wc;
    const float* V = (g == 0) ? Vf : (g == 1) ? Vi : (g == 2) ? Vo : Vc;
    float4 vw = reinterpret_cast<const float4*>(W)[(size_t)j * 256 + t];
    hsplit_store4(vw, g_Whi + (size_t)row * KDIM + 4 * t,
                      g_Wlo + (size_t)row * KDIM + 4 * t);
    float4 vv = reinterpret_cast<const float4*>(V)[(size_t)j * 256 + t];
    hsplit_store4(vv, g_Whi + (size_t)row * KDIM + IDIM + 4 * t,
                      g_Wlo + (size_t)row * KDIM + IDIM + 4 * t);
}

// ===================== kernel 3: combined bias (interleaved) =====================
__global__ void bias_kernel(const float* __restrict__ bWf, const float* __restrict__ bVf, const float* __restrict__ bf_,
                            const float* __restrict__ bWi, const float* __restrict__ bVi, const float* __restrict__ bi_,
                            const float* __restrict__ bWo, const float* __restrict__ bVo, const float* __restrict__ bo_,
                            const float* __restrict__ bWc, const float* __restrict__ bVc, const float* __restrict__ bc_) {
    int n = blockIdx.x * blockDim.x + threadIdx.x;
    if (n >= NDIM) return;
    int g = n >> 10, j = n & 1023;
    const float* a = (g == 0) ? bWf : (g == 1) ? bWi : (g == 2) ? bWo : bWc;
    const float* b = (g == 0) ? bVf : (g == 1) ? bVi : (g == 2) ? bVo : bVc;
    const float* c = (g == 0) ? bf_ : (g == 1) ? bi_ : (g == 2) ? bo_ : bc_;
    g_bias[(j << 2) | g] = a[j] + b[j] + c[j];
}

// ===================== kernel 4: pipelined GEMM + fused LSTM epilogue =====================
// gates = A*Whi^T + A*Wlo^T  (fp16 inputs, fp32 accum), then activations -> out
#define BM 128
#define BN 128
#define BK 32
#define NK (KDIM / BK)          // 64 k-tiles
#define TOTAL_TILES 1024
#define GRID_CTAS 888           // 3 * 296; 136 CTAs do 2 tiles
#define BUF_BYTES (128 * 64)    // 8192: 128 rows x 64B (pitch 64, swizzled)
#define STAGE_BYTES (3 * BUF_BYTES)    // 24576: A, Whi, Wlo
#define NSTAGES 4
#define GEMM_SMEM (NSTAGES * STAGE_BYTES)  // 98304
#define EPITCH 132              // floats per gates row in smem epilogue

// swizzled byte offset of 16B chunk c (0..3) in row r, pitch 64.
// swz(r+16, c) == swz(r, c) + 1024 (swizzle term invariant under r += 16).
__device__ __forceinline__ uint32_t swz(int r, int c) {
    return (uint32_t)(r * 64 + ((c ^ ((r >> 1) & 3)) << 4));
}

__global__ void __launch_bounds__(256, 2) gemm_kernel(const float* __restrict__ c_prev,
                                                      float* __restrict__ out, int n_out) {
    extern __shared__ char smem[];
    uint32_t sb = smem_to_u32(smem);
    int tid = threadIdx.x, wid = tid >> 5, lid = tid & 31;
    int wm = (wid >> 1) * 32;   // 4x2 warp grid, warp tile 32x64
    int wn = (wid & 1) * 64;
    int lrow = lid & 15;
    int cbase = lid >> 4;       // 0 or 1: second 16B chunk within k-step

    // ---- thread-invariant ldmatrix base offsets
    uint32_t offA0[2], offW0[2];
    #pragma unroll
    for (int ks = 0; ks < 2; ++ks) {
        int cidx = ks * 2 + cbase;
        offA0[ks] = swz(wm + lrow, cidx);                      // A buffer at 0
        offW0[ks] = swz(wn + lrow, cidx) + (uint32_t)BUF_BYTES; // Whi at +BUF, Wlo at +2*BUF
    }

    // ---- thread-invariant cp.async producer offsets
    int ls_r0 = tid >> 2, ls_c0 = tid & 3;            // q = tid
    int ls_r1 = (tid + 256) >> 2;                     // q = tid + 256 (same chunk col)
    uint32_t ls_soff0 = swz(ls_r0, ls_c0);
    uint32_t ls_soff1 = swz(ls_r1, ls_c0);
    size_t ls_goff0 = (size_t)ls_r0 * KDIM + ls_c0 * 8;
    size_t ls_goff1 = (size_t)ls_r1 * KDIM + ls_c0 * 8;

    for (int t = blockIdx.x; t < TOTAL_TILES; t += GRID_CTAS) {
        int m0 = (t >> 5) * BM;
        int n0 = (t & 31) * BN;
        int j_base = n0 >> 2;   // interleaved: 32 j's per CTA tile

        const __half* pA0   = g_A   + (size_t)m0 * KDIM + ls_goff0;
        const __half* pA1   = g_A   + (size_t)m0 * KDIM + ls_goff1;
        const __half* pWhi0 = g_Whi + (size_t)n0 * KDIM + ls_goff0;
        const __half* pWhi1 = g_Whi + (size_t)n0 * KDIM + ls_goff1;
        const __half* pWlo0 = g_Wlo + (size_t)n0 * KDIM + ls_goff0;
        const __half* pWlo1 = g_Wlo + (size_t)n0 * KDIM + ls_goff1;

        #define LOAD_STAGE(stage, kt) do {                                      \
            uint32_t s0_ = sb + (uint32_t)(stage) * STAGE_BYTES;                \
            int ko_ = (kt) * BK;                                                \
            cp16(s0_ + ls_soff0,                 pA0 + ko_);                    \
            cp16(s0_ + ls_soff1,                 pA1 + ko_);                    \
            cp16(s0_ + BUF_BYTES + ls_soff0,     pWhi0 + ko_);                  \
            cp16(s0_ + BUF_BYTES + ls_soff1,     pWhi1 + ko_);                  \
            cp16(s0_ + 2 * BUF_BYTES + ls_soff0, pWlo0 + ko_);                  \
            cp16(s0_ + 2 * BUF_BYTES + ls_soff1, pWlo1 + ko_);                  \
            CP_COMMIT();                                                        \
        } while (0)

        float acc[2][8][4];
        #pragma unroll
        for (int i = 0; i < 2; ++i)
            #pragma unroll
            for (int j = 0; j < 8; ++j)
                #pragma unroll
                for (int k = 0; k < 4; ++k) acc[i][j][k] = 0.0f;

        // prologue: stages 0,1,2 (prefetch distance 3)
        LOAD_STAGE(0, 0);
        LOAD_STAGE(1, 1);
        LOAD_STAGE(2, 2);

        for (int kt = 0; kt < NK; ++kt) {
            if (kt < NK - 2)       { CP_WAIT(2); }
            else if (kt == NK - 2) { CP_WAIT(1); }
            else                   { CP_WAIT(0); }
            __syncthreads();   // tile kt visible to all; frees buffer (kt+3)%4

            uint32_t cur = sb + (uint32_t)(kt & (NSTAGES - 1)) * STAGE_BYTES;

            #pragma unroll
            for (int ks = 0; ks < 2; ++ks) {
                uint32_t aB = cur + offA0[ks];   // A fragment base
                uint32_t wB = cur + offW0[ks];   // Whi fragment base

                uint32_t a[2][4], w0[4][4];
                ldsm4(a[0], aB);
                ldsm4(a[1], aB + 1024u);
                #pragma unroll
                for (int bn = 0; bn < 4; ++bn)
                    ldsm4(w0[bn], wB + (uint32_t)(bn * 1024));

                // pass 1: A * Whi
                #pragma unroll
                for (int am = 0; am < 2; ++am)
                    #pragma unroll
                    for (int bn = 0; bn < 4; ++bn) {
                        mma16816(acc[am][2 * bn],     a[am], w0[bn][0], w0[bn][2]);
                        mma16816(acc[am][2 * bn + 1], a[am], w0[bn][1], w0[bn][3]);
                    }

                // pass 2: A * Wlo  (Wlo buffer = Whi buffer + BUF_BYTES)
                uint32_t w1[4][4];
                #pragma unroll
                for (int bn = 0; bn < 4; ++bn)
                    ldsm4(w1[bn], wB + (uint32_t)(BUF_BYTES + bn * 1024));
                #pragma unroll
                for (int am = 0; am < 2; ++am)
                    #pragma unroll
                    for (int bn = 0; bn < 4; ++bn) {
                        mma16816(acc[am][2 * bn],     a[am], w1[bn][0], w1[bn][2]);
                        mma16816(acc[am][2 * bn + 1], a[am], w1[bn][1], w1[bn][3]);
                    }
            }

            // prefetch tile kt+3 (top barrier of next iter protects WAR)
            if (kt + 3 < NK)
                LOAD_STAGE((kt + 3) & (NSTAGES - 1), kt + 3);
        }
        #undef LOAD_STAGE

        // ===== fused epilogue: acc -> smem -> activations -> out =====
        __syncthreads();   // done reading stage buffers; reuse smem for gates
        float* sg = reinterpret_cast<float*>(smem);   // [128][EPITCH]
        int gid = lid >> 2, tig = lid & 3;
        #pragma unroll
        for (int am = 0; am < 2; ++am) {
            #pragma unroll
            for (int bn = 0; bn < 8; ++bn) {
                const float* c = acc[am][bn];
                int row = wm + am * 16 + gid;
                int col = wn + bn * 8 + tig * 2;
                sg[row * EPITCH + col]           = c[0];
                sg[row * EPITCH + col + 1]       = c[1];
                sg[(row + 8) * EPITCH + col]     = c[2];
                sg[(row + 8) * EPITCH + col + 1] = c[3];
            }
        }
        __syncthreads();

        const int BH = BDIM * HDIM;
        #pragma unroll
        for (int i = 0; i < 16; ++i) {
            int idx = tid + i * 256;       // 128 rows x 32 j
            int row = idx >> 5, lj = idx & 31;
            float4 gv = *reinterpret_cast<const float4*>(&sg[row * EPITCH + lj * 4]);
            int jg = j_base + lj;
            float4 bv = *reinterpret_cast<const float4*>(&g_bias[jg * 4]);
            float fp = gv.x + bv.x, ip = gv.y + bv.y, op = gv.z + bv.z, cp = gv.w + bv.w;
            float ft = 1.0f / (1.0f + expf(-fp));
            float it = 1.0f / (1.0f + expf(-ip));
            float ot = 1.0f / (1.0f + expf(-op));
            float ct = tanhf(cp);
            int m = m0 + row;
            int oidx = m * HDIM + jg;
            float cpv = c_prev[oidx];
            float cn = ft * cpv + it * cpv + g_mask[m] * (it * ct);
            float hn = ot * tanhf(cn);
            out[oidx] = hn;
            if (BH + oidx < n_out)     out[BH + oidx] = cn;
            if (2 * BH + oidx < n_out) out[2 * BH + oidx] = ct;
        }
        __syncthreads();   // epilogue reads done before next tile's cp.async writes
    }
}

// ===================== launcher =====================
extern "C" void kernel_launch(void* const* d_in, const int* in_sizes, int n_in,
                              void* d_out, int out_size) {
    (void)n_in;
    const float* x      = (const float*)d_in[0];
    const float* h_prev = (const float*)d_in[1];
    const float* c_prev = (const float*)d_in[2];
    // d_in[3] = c_prev_tilde_dummy (unused)

    // Input order detection (dict order vs signature order); see round-2 notes.
    const float *W[4], *V[4], *bW[4], *bV[4], *bx[4];
    if (in_sizes[8] > 100000) {
        for (int g = 0; g < 4; ++g) {   // dict order
            W[g]  = (const float*)d_in[4 + 4 * g];
            bW[g] = (const float*)d_in[5 + 4 * g];
            V[g]  = (const float*)d_in[6 + 4 * g];
            bV[g] = (const float*)d_in[7 + 4 * g];
            bx[g] = (const float*)d_in[20 + g];
        }
    } else {
        for (int g = 0; g < 4; ++g) {   // signature order
            W[g]  = (const float*)d_in[4 + 5 * g];
            bW[g] = (const float*)d_in[5 + 5 * g];
            V[g]  = (const float*)d_in[6 + 5 * g];
            bV[g] = (const float*)d_in[7 + 5 * g];
            bx[g] = (const float*)d_in[8 + 5 * g];
        }
    }

    convert_A_kernel<<<BDIM, 256>>>(x, h_prev);
    convert_W_kernel<<<NDIM, 256>>>(W[0], W[1], W[2], W[3], V[0], V[1], V[2], V[3]);
    bias_kernel<<<NDIM / 256, 256>>>(bW[0], bV[0], bx[0], bW[1], bV[1], bx[1],
                                     bW[2], bV[2], bx[2], bW[3], bV[3], bx[3]);

    static bool attr_set = false;
    if (!attr_set) {
        cudaFuncSetAttribute(gemm_kernel, cudaFuncAttributeMaxDynamicSharedMemorySize,
                             (int)GEMM_SMEM);
        attr_set = true;
    }
    gemm_kernel<<<GRID_CTAS, 256, GEMM_SMEM>>>(c_prev, (float*)d_out, out_size);
}

// round 8
// speedup vs baseline: 3.0416x; 1.6356x over previous
#include <cuda_runtime.h>
#include <cuda_fp16.h>
#include <cstdint>

// ===================== problem dims =====================
#define BDIM 4096
#define IDIM 1024
#define HDIM 1024
#define KDIM 2048   // I + H
#define NDIM 4096   // 4 * H, INTERLEAVED: n = j*4 + g  (g in {f,i,o,c})

// ===================== device scratch (static, allowed) =====================
__device__ __align__(256) __half g_A[(size_t)BDIM * KDIM];    // fp16(x|h)
__device__ __align__(256) __half g_W[(size_t)NDIM * KDIM];    // fp16(W), interleaved rows
__device__ __align__(256) float  g_bias[NDIM];                // interleaved j*4+g
__device__ __align__(256) float  g_mask[BDIM];

// ===================== small PTX helpers (sm_80+ features only) =====================
__device__ __forceinline__ uint32_t smem_to_u32(const void* p) {
    uint32_t a;
    asm("{ .reg .u64 t; cvta.to.shared.u64 t, %1; cvt.u32.u64 %0, t; }" : "=r"(a) : "l"(p));
    return a;
}

__device__ __forceinline__ void cp16(uint32_t saddr, const void* g) {
    asm volatile("cp.async.cg.shared.global [%0], [%1], 16;" :: "r"(saddr), "l"(g) : "memory");
}

#define CP_COMMIT() asm volatile("cp.async.commit_group;" ::: "memory")
#define CP_WAIT(N)  asm volatile("cp.async.wait_group %0;" :: "n"(N) : "memory")

__device__ __forceinline__ void ldsm4(uint32_t* r, uint32_t addr) {
    asm volatile("ldmatrix.sync.aligned.m8n8.x4.shared.b16 {%0,%1,%2,%3}, [%4];"
                 : "=r"(r[0]), "=r"(r[1]), "=r"(r[2]), "=r"(r[3]) : "r"(addr));
}

__device__ __forceinline__ void mma16816(float* c, const uint32_t* a, uint32_t b0, uint32_t b1) {
    asm volatile(
        "mma.sync.aligned.m16n8k16.row.col.f32.f16.f16.f32 "
        "{%0,%1,%2,%3}, {%4,%5,%6,%7}, {%8,%9}, {%0,%1,%2,%3};"
        : "+f"(c[0]), "+f"(c[1]), "+f"(c[2]), "+f"(c[3])
        : "r"(a[0]), "r"(a[1]), "r"(a[2]), "r"(a[3]), "r"(b0), "r"(b1));
}

// ===================== conversion helpers =====================
__device__ __forceinline__ uint32_t pkh2(__half a, __half b) {
    __half2 t = __halves2half2(a, b);
    return *reinterpret_cast<uint32_t*>(&t);
}

// store 4 fp16 and return sum of squares
__device__ __forceinline__ float h_store4(float4 v, __half* dst) {
    uint2 hv = make_uint2(pkh2(__float2half_rn(v.x), __float2half_rn(v.y)),
                          pkh2(__float2half_rn(v.z), __float2half_rn(v.w)));
    *reinterpret_cast<uint2*>(dst) = hv;
    return v.x * v.x + v.y * v.y + v.z * v.z + v.w * v.w;
}

// ===================== kernel 1: convert A = [x | h_prev] + silence mask =====================
__global__ void convert_A_kernel(const float* __restrict__ x, const float* __restrict__ h) {
    int m = blockIdx.x;
    int t = threadIdx.x;  // 256
    float4 vx = reinterpret_cast<const float4*>(x)[(size_t)m * 256 + t];
    float ss = h_store4(vx, g_A + (size_t)m * KDIM + 4 * t);
    float4 vh = reinterpret_cast<const float4*>(h)[(size_t)m * 256 + t];
    h_store4(vh, g_A + (size_t)m * KDIM + IDIM + 4 * t);

    __shared__ float red[256];
    red[t] = ss;
    __syncthreads();
    for (int s = 128; s > 0; s >>= 1) {
        if (t < s) red[t] += red[t + s];
        __syncthreads();
    }
    if (t == 0) g_mask[m] = (red[0] > 1e-6f) ? 1.0f : 0.0f;  // norm > 0.001
}

// ===================== kernel 2: convert packed weights (interleaved rows, fp16) ==========
__global__ void convert_W_kernel(const float* __restrict__ Wf, const float* __restrict__ Wi,
                                 const float* __restrict__ Wo, const float* __restrict__ Wc,
                                 const float* __restrict__ Vf, const float* __restrict__ Vi,
                                 const float* __restrict__ Vo, const float* __restrict__ Vc) {
    int n = blockIdx.x;     // 0..4095 (gate-major source index)
    int t = threadIdx.x;    // 256
    int g = n >> 10, j = n & 1023;
    int row = (j << 2) | g;  // interleaved destination row
    const float* W = (g == 0) ? Wf : (g == 1) ? Wi : (g == 2) ? Wo : Wc;
    const float* V = (g == 0) ? Vf : (g == 1) ? Vi : (g == 2) ? Vo : Vc;
    float4 vw = reinterpret_cast<const float4*>(W)[(size_t)j * 256 + t];
    h_store4(vw, g_W + (size_t)row * KDIM + 4 * t);
    float4 vv = reinterpret_cast<const float4*>(V)[(size_t)j * 256 + t];
    h_store4(vv, g_W + (size_t)row * KDIM + IDIM + 4 * t);
}

// ===================== kernel 3: combined bias (interleaved) =====================
__global__ void bias_kernel(const float* __restrict__ bWf, const float* __restrict__ bVf, const float* __restrict__ bf_,
                            const float* __restrict__ bWi, const float* __restrict__ bVi, const float* __restrict__ bi_,
                            const float* __restrict__ bWo, const float* __restrict__ bVo, const float* __restrict__ bo_,
                            const float* __restrict__ bWc, const float* __restrict__ bVc, const float* __restrict__ bc_) {
    int n = blockIdx.x * blockDim.x + threadIdx.x;
    if (n >= NDIM) return;
    int g = n >> 10, j = n & 1023;
    const float* a = (g == 0) ? bWf : (g == 1) ? bWi : (g == 2) ? bWo : bWc;
    const float* b = (g == 0) ? bVf : (g == 1) ? bVi : (g == 2) ? bVo : bVc;
    const float* c = (g == 0) ? bf_ : (g == 1) ? bi_ : (g == 2) ? bo_ : bc_;
    g_bias[(j << 2) | g] = a[j] + b[j] + c[j];
}

// ===================== kernel 4: pipelined GEMM + fused LSTM epilogue =====================
// gates = A*W^T  (fp16 inputs, fp32 accum), then activations -> out
#define BM 128
#define BN 128
#define BK 32
#define NK (KDIM / BK)          // 64 k-tiles
#define TOTAL_TILES 1024
#define GRID_CTAS 888           // 3 * 296; 136 CTAs do 2 tiles
#define BUF_BYTES (128 * 64)    // 8192: 128 rows x 64B (pitch 64, swizzled)
#define STAGE_BYTES (2 * BUF_BYTES)    // 16384: A, W
#define NSTAGES 4
#define EPITCH 132              // floats per gates row in smem epilogue
#define GEMM_SMEM (128 * EPITCH * 4)   // 67584 >= NSTAGES*STAGE_BYTES (65536)

// swizzled byte offset of 16B chunk c (0..3) in row r, pitch 64.
// swz(r+16, c) == swz(r, c) + 1024 (swizzle term invariant under r += 16).
__device__ __forceinline__ uint32_t swz(int r, int c) {
    return (uint32_t)(r * 64 + ((c ^ ((r >> 1) & 3)) << 4));
}

__global__ void __launch_bounds__(256, 2) gemm_kernel(const float* __restrict__ c_prev,
                                                      float* __restrict__ out, int n_out) {
    extern __shared__ char smem[];
    uint32_t sb = smem_to_u32(smem);
    int tid = threadIdx.x, wid = tid >> 5, lid = tid & 31;
    int wm = (wid >> 1) * 32;   // 4x2 warp grid, warp tile 32x64
    int wn = (wid & 1) * 64;
    int lrow = lid & 15;
    int cbase = lid >> 4;       // 0 or 1: second 16B chunk within k-step

    // ---- thread-invariant ldmatrix base offsets
    uint32_t offA0[2], offW0[2];
    #pragma unroll
    for (int ks = 0; ks < 2; ++ks) {
        int cidx = ks * 2 + cbase;
        offA0[ks] = swz(wm + lrow, cidx);                       // A buffer at 0
        offW0[ks] = swz(wn + lrow, cidx) + (uint32_t)BUF_BYTES; // W buffer at +BUF
    }

    // ---- thread-invariant cp.async producer offsets
    int ls_r0 = tid >> 2, ls_c0 = tid & 3;            // q = tid
    int ls_r1 = (tid + 256) >> 2;                     // q = tid + 256 (same chunk col)
    uint32_t ls_soff0 = swz(ls_r0, ls_c0);
    uint32_t ls_soff1 = swz(ls_r1, ls_c0);
    size_t ls_goff0 = (size_t)ls_r0 * KDIM + ls_c0 * 8;
    size_t ls_goff1 = (size_t)ls_r1 * KDIM + ls_c0 * 8;

    for (int t = blockIdx.x; t < TOTAL_TILES; t += GRID_CTAS) {
        int m0 = (t >> 5) * BM;
        int n0 = (t & 31) * BN;
        int j_base = n0 >> 2;   // interleaved: 32 j's per CTA tile

        const __half* pA0 = g_A + (size_t)m0 * KDIM + ls_goff0;
        const __half* pA1 = g_A + (size_t)m0 * KDIM + ls_goff1;
        const __half* pW0 = g_W + (size_t)n0 * KDIM + ls_goff0;
        const __half* pW1 = g_W + (size_t)n0 * KDIM + ls_goff1;

        #define LOAD_STAGE(stage, kt) do {                                      \
            uint32_t s0_ = sb + (uint32_t)(stage) * STAGE_BYTES;                \
            int ko_ = (kt) * BK;                                                \
            cp16(s0_ + ls_soff0,             pA0 + ko_);                        \
            cp16(s0_ + ls_soff1,             pA1 + ko_);                        \
            cp16(s0_ + BUF_BYTES + ls_soff0, pW0 + ko_);                        \
            cp16(s0_ + BUF_BYTES + ls_soff1, pW1 + ko_);                        \
            CP_COMMIT();                                                        \
        } while (0)

        float acc[2][8][4];
        #pragma unroll
        for (int i = 0; i < 2; ++i)
            #pragma unroll
            for (int j = 0; j < 8; ++j)
                #pragma unroll
                for (int k = 0; k < 4; ++k) acc[i][j][k] = 0.0f;

        // prologue: stages 0,1,2 (prefetch distance 3)
        LOAD_STAGE(0, 0);
        LOAD_STAGE(1, 1);
        LOAD_STAGE(2, 2);

        for (int kt = 0; kt < NK; ++kt) {
            if (kt < NK - 2)       { CP_WAIT(2); }
            else if (kt == NK - 2) { CP_WAIT(1); }
            else                   { CP_WAIT(0); }
            __syncthreads();   // tile kt visible to all; frees buffer (kt+3)%4

            uint32_t cur = sb + (uint32_t)(kt & (NSTAGES - 1)) * STAGE_BYTES;

            #pragma unroll
            for (int ks = 0; ks < 2; ++ks) {
                uint32_t aB = cur + offA0[ks];   // A fragment base
                uint32_t wB = cur + offW0[ks];   // W fragment base

                uint32_t a[2][4], w0[4][4];
                ldsm4(a[0], aB);
                ldsm4(a[1], aB + 1024u);
                #pragma unroll
                for (int bn = 0; bn < 4; ++bn)
                    ldsm4(w0[bn], wB + (uint32_t)(bn * 1024));

                #pragma unroll
                for (int am = 0; am < 2; ++am)
                    #pragma unroll
                    for (int bn = 0; bn < 4; ++bn) {
                        mma16816(acc[am][2 * bn],     a[am], w0[bn][0], w0[bn][2]);
                        mma16816(acc[am][2 * bn + 1], a[am], w0[bn][1], w0[bn][3]);
                    }
            }

            // prefetch tile kt+3 (top barrier of next iter protects WAR)
            if (kt + 3 < NK)
                LOAD_STAGE((kt + 3) & (NSTAGES - 1), kt + 3);
        }
        #undef LOAD_STAGE

        // ===== fused epilogue: acc -> smem -> activations -> out =====
        __syncthreads();   // done reading stage buffers; reuse smem for gates
        float* sg = reinterpret_cast<float*>(smem);   // [128][EPITCH]
        int gid = lid >> 2, tig = lid & 3;
        #pragma unroll
        for (int am = 0; am < 2; ++am) {
            #pragma unroll
            for (int bn = 0; bn < 8; ++bn) {
                const float* c = acc[am][bn];
                int row = wm + am * 16 + gid;
                int col = wn + bn * 8 + tig * 2;
                sg[row * EPITCH + col]           = c[0];
                sg[row * EPITCH + col + 1]       = c[1];
                sg[(row + 8) * EPITCH + col]     = c[2];
                sg[(row + 8) * EPITCH + col + 1] = c[3];
            }
        }
        __syncthreads();

        const int BH = BDIM * HDIM;
        #pragma unroll
        for (int i = 0; i < 16; ++i) {
            int idx = tid + i * 256;       // 128 rows x 32 j
            int row = idx >> 5, lj = idx & 31;
            float4 gv = *reinterpret_cast<const float4*>(&sg[row * EPITCH + lj * 4]);
            int jg = j_base + lj;
            float4 bv = *reinterpret_cast<const float4*>(&g_bias[jg * 4]);
            float fp = gv.x + bv.x, ip = gv.y + bv.y, op = gv.z + bv.z, cp = gv.w + bv.w;
            float ft = 1.0f / (1.0f + expf(-fp));
            float it = 1.0f / (1.0f + expf(-ip));
            float ot = 1.0f / (1.0f + expf(-op));
            float ct = tanhf(cp);
            int m = m0 + row;
            int oidx = m * HDIM + jg;
            float cpv = c_prev[oidx];
            float cn = ft * cpv + it * cpv + g_mask[m] * (it * ct);
            float hn = ot * tanhf(cn);
            out[oidx] = hn;
            if (BH + oidx < n_out)     out[BH + oidx] = cn;
            if (2 * BH + oidx < n_out) out[2 * BH + oidx] = ct;
        }
        __syncthreads();   // epilogue reads done before next tile's cp.async writes
    }
}

// ===================== launcher =====================
extern "C" void kernel_launch(void* const* d_in, const int* in_sizes, int n_in,
                              void* d_out, int out_size) {
    (void)n_in;
    const float* x      = (const float*)d_in[0];
    const float* h_prev = (const float*)d_in[1];
    const float* c_prev = (const float*)d_in[2];
    // d_in[3] = c_prev_tilde_dummy (unused)

    // Input order detection (dict order vs signature order); see round-2 notes.
    const float *W[4], *V[4], *bW[4], *bV[4], *bx[4];
    if (in_sizes[8] > 100000) {
        for (int g = 0; g < 4; ++g) {   // dict order
            W[g]  = (const float*)d_in[4 + 4 * g];
            bW[g] = (const float*)d_in[5 + 4 * g];
            V[g]  = (const float*)d_in[6 + 4 * g];
            bV[g] = (const float*)d_in[7 + 4 * g];
            bx[g] = (const float*)d_in[20 + g];
        }
    } else {
        for (int g = 0; g < 4; ++g) {   // signature order
            W[g]  = (const float*)d_in[4 + 5 * g];
            bW[g] = (const float*)d_in[5 + 5 * g];
            V[g]  = (const float*)d_in[6 + 5 * g];
            bV[g] = (const float*)d_in[7 + 5 * g];
            bx[g] = (const float*)d_in[8 + 5 * g];
        }
    }

    convert_A_kernel<<<BDIM, 256>>>(x, h_prev);
    convert_W_kernel<<<NDIM, 256>>>(W[0], W[1], W[2], W[3], V[0], V[1], V[2], V[3]);
    bias_kernel<<<NDIM / 256, 256>>>(bW[0], bV[0], bx[0], bW[1], bV[1], bx[1],
                                     bW[2], bV[2], bx[2], bW[3], bV[3], bx[3]);

    static bool attr_set = false;
    if (!attr_set) {
        cudaFuncSetAttribute(gemm_kernel, cudaFuncAttributeMaxDynamicSharedMemorySize,
                             (int)GEMM_SMEM);
        attr_set = true;
    }
    gemm_kernel<<<GRID_CTAS, 256, GEMM_SMEM>>>(c_prev, (float*)d_out, out_size);
}